// round 3
// baseline (speedup 1.0000x reference)
#include <cuda_runtime.h>

// FPN Pooler: multi-level ROIAlign, smem-staged windows.
// feats NCHW f32: f0 [2,256,200,200], f1 [2,256,100,100], f2 [2,256,50,50], f3 [2,256,25,25]
// boxes [1000,4], img_ids [1000] -> out [1000,256,7,7] f32

#define P 14            // OUT*SR sample grid per axis
#define CPB 64          // channels per block (4 blocks per box)
#define CH 4            // channels staged per iteration
#define TILE_F 1281     // floats per channel tile (max footprint ~1100), odd
#define ITEMS 196       // CH * 49 bins
#define BLOCK 224
#define NWARP 7

__global__ __launch_bounds__(BLOCK) void pooler_kernel(
    const float* __restrict__ f0, const float* __restrict__ f1,
    const float* __restrict__ f2, const float* __restrict__ f3,
    const float* __restrict__ boxes, const int* __restrict__ img_ids,
    float* __restrict__ out)
{
    const int bx  = blockIdx.x;
    const int n   = bx >> 2;
    const int cq  = (bx & 3) * CPB;
    const int tid = threadIdx.x;

    __shared__ float s_tile[CH * TILE_F];
    __shared__ int   s_rawx0[P], s_rawx1[P], s_rawy0[P], s_rawy1[P];
    __shared__ int   s_cx0[P], s_cx1[P], s_oy0[P], s_oy1[P];
    __shared__ float s_ax0[P], s_ax1[P], s_ay0[P], s_ay1[P];

    // ---- per-box geometry scalars (computed redundantly by all threads) ----
    const float bx1 = boxes[4*n+0], by1 = boxes[4*n+1];
    const float bx2 = boxes[4*n+2], by2 = boxes[4*n+3];
    const float area = (bx2 - bx1) * (by2 - by1);
    const float sq   = sqrtf(area);
    float lf = floorf(4.0f + log2f(sq / 224.0f + 1e-6f));
    lf = fminf(fmaxf(lf, 2.0f), 5.0f);
    const int lvl = (int)lf - 2;

    int H, W; float scale; const float* fp;
    switch (lvl) {
        case 0:  H = 200; W = 200; scale = 0.25f;    fp = f0; break;
        case 1:  H = 100; W = 100; scale = 0.125f;   fp = f1; break;
        case 2:  H = 50;  W = 50;  scale = 0.0625f;  fp = f2; break;
        default: H = 25;  W = 25;  scale = 0.03125f; fp = f3; break;
    }
    const int HW  = H * W;
    const int img = __ldg(img_ids + n);
    const float* gbase = fp + (size_t)img * 256 * HW;

    const float rx1 = bx1 * scale, ry1 = by1 * scale;
    const float roi_w = fmaxf(bx2 * scale - rx1, 1.0f);
    const float roi_h = fmaxf(by2 * scale - ry1, 1.0f);
    const float bw = roi_w * (1.0f / 7.0f);
    const float bh = roi_h * (1.0f / 7.0f);

    // ---- phase 1: per-axis sample tables (x by threads 0..13, y by 16..29) ----
    if (tid < P) {
        const int i = tid, p = i >> 1, r = i & 1;
        const float xg = rx1 + (float)p * bw + ((float)r + 0.5f) * bw * 0.5f;
        const float vx = (xg >= -1.0f && xg <= (float)W) ? 0.5f : 0.0f;  // fold 0.5
        float x = fminf(fmaxf(xg, 0.0f), (float)(W - 1));
        const int x0 = (int)x;                 // x >= 0 => trunc == floor
        const int x1i = min(x0 + 1, W - 1);
        const float lx = x - (float)x0;
        s_rawx0[i] = x0; s_rawx1[i] = x1i;
        s_ax0[i] = vx * (1.0f - lx);
        s_ax1[i] = vx * lx;
    } else if (tid >= 16 && tid < 16 + P) {
        const int i = tid - 16, p = i >> 1, r = i & 1;
        const float yg = ry1 + (float)p * bh + ((float)r + 0.5f) * bh * 0.5f;
        const float vy = (yg >= -1.0f && yg <= (float)H) ? 0.5f : 0.0f;
        float y = fminf(fmaxf(yg, 0.0f), (float)(H - 1));
        const int y0 = (int)y;
        const int y1i = min(y0 + 1, H - 1);
        const float ly = y - (float)y0;
        s_rawy0[i] = y0; s_rawy1[i] = y1i;
        s_ay0[i] = vy * (1.0f - ly);
        s_ay1[i] = vy * ly;
    }
    __syncthreads();

    // window bounds (samples are monotonic in both axes)
    const int clo = s_rawx0[0], rlo = s_rawy0[0];
    const int nc  = s_rawx1[P-1] - clo + 1;
    const int nr  = s_rawy1[P-1] - rlo + 1;
    const int stride = nc | 1;                 // odd stride: bank stagger

    // ---- phase 2: tile-relative offsets ----
    if (tid < P) {
        s_cx0[tid] = s_rawx0[tid] - clo;
        s_cx1[tid] = s_rawx1[tid] - clo;
    } else if (tid >= 16 && tid < 16 + P) {
        const int i = tid - 16;
        s_oy0[i] = (s_rawy0[i] - rlo) * stride;
        s_oy1[i] = (s_rawy1[i] - rlo) * stride;
    }
    __syncthreads();

    // ---- hoist per-bin indices + folded coefficients into registers ----
    int   iAA0=0, iAA1=0, iAA2=0, iAA3=0, iAB0=0, iAB1=0, iAB2=0, iAB3=0;
    int   iBA0=0, iBA1=0, iBA2=0, iBA3=0, iBB0=0, iBB1=0, iBB2=0, iBB3=0;
    float cAA0=0, cAA1=0, cAA2=0, cAA3=0, cAB0=0, cAB1=0, cAB2=0, cAB3=0;
    float cBA0=0, cBA1=0, cBA2=0, cBA3=0, cBB0=0, cBB1=0, cBB2=0, cBB3=0;
    const float* tp = s_tile;
    float* outp = out;

    if (tid < ITEMS) {
        const int ch_l = tid / 49;
        const int bin  = tid % 49;
        const int ph = bin / 7, pw = bin % 7;
        const int iyA = 2*ph, iyB = iyA + 1;
        const int ixA = 2*pw, ixB = ixA + 1;

        const int oA0 = s_oy0[iyA], oA1 = s_oy1[iyA];
        const int oB0 = s_oy0[iyB], oB1 = s_oy1[iyB];
        const int cA0 = s_cx0[ixA], cA1 = s_cx1[ixA];
        const int cB0 = s_cx0[ixB], cB1 = s_cx1[ixB];
        const float ayA0 = s_ay0[iyA], ayA1 = s_ay1[iyA];
        const float ayB0 = s_ay0[iyB], ayB1 = s_ay1[iyB];
        const float axA0 = s_ax0[ixA], axA1 = s_ax1[ixA];
        const float axB0 = s_ax0[ixB], axB1 = s_ax1[ixB];

        iAA0 = oA0 + cA0; cAA0 = ayA0 * axA0;
        iAA1 = oA0 + cA1; cAA1 = ayA0 * axA1;
        iAA2 = oA1 + cA0; cAA2 = ayA1 * axA0;
        iAA3 = oA1 + cA1; cAA3 = ayA1 * axA1;

        iAB0 = oA0 + cB0; cAB0 = ayA0 * axB0;
        iAB1 = oA0 + cB1; cAB1 = ayA0 * axB1;
        iAB2 = oA1 + cB0; cAB2 = ayA1 * axB0;
        iAB3 = oA1 + cB1; cAB3 = ayA1 * axB1;

        iBA0 = oB0 + cA0; cBA0 = ayB0 * axA0;
        iBA1 = oB0 + cA1; cBA1 = ayB0 * axA1;
        iBA2 = oB1 + cA0; cBA2 = ayB1 * axA0;
        iBA3 = oB1 + cA1; cBA3 = ayB1 * axA1;

        iBB0 = oB0 + cB0; cBB0 = ayB0 * axB0;
        iBB1 = oB0 + cB1; cBB1 = ayB0 * axB1;
        iBB2 = oB1 + cB0; cBB2 = ayB1 * axB0;
        iBB3 = oB1 + cB1; cBB3 = ayB1 * axB1;

        tp   = s_tile + ch_l * TILE_F;
        outp = out + (size_t)n * 12544 + (size_t)(cq + ch_l) * 49 + bin;
    }

    // ---- main loop: stage CH channel windows, compute 4*49 bins ----
    const int warp = tid >> 5, lane = tid & 31;
    const int gRow0 = rlo * W + clo;

    for (int cb = 0; cb < CPB; cb += CH) {
        // stage (coalesced rows)
        #pragma unroll
        for (int ch_l = 0; ch_l < CH; ++ch_l) {
            const float* gp = gbase + (size_t)(cq + cb + ch_l) * HW + gRow0;
            float* t = s_tile + ch_l * TILE_F;
            for (int r = warp; r < nr; r += NWARP) {
                const float* grow = gp + r * W;
                float* trow = t + r * stride;
                for (int c = lane; c < nc; c += 32)
                    trow[c] = __ldg(grow + c);
            }
        }
        __syncthreads();

        if (tid < ITEMS) {
            float acc;
            acc  = cAA0 * tp[iAA0];
            acc += cAA1 * tp[iAA1];
            acc += cAA2 * tp[iAA2];
            acc += cAA3 * tp[iAA3];
            acc += cAB0 * tp[iAB0];
            acc += cAB1 * tp[iAB1];
            acc += cAB2 * tp[iAB2];
            acc += cAB3 * tp[iAB3];
            acc += cBA0 * tp[iBA0];
            acc += cBA1 * tp[iBA1];
            acc += cBA2 * tp[iBA2];
            acc += cBA3 * tp[iBA3];
            acc += cBB0 * tp[iBB0];
            acc += cBB1 * tp[iBB1];
            acc += cBB2 * tp[iBB2];
            acc += cBB3 * tp[iBB3];
            *outp = acc;
            outp += ITEMS;   // next CH channels
        }
        __syncthreads();
    }
}

extern "C" void kernel_launch(void* const* d_in, const int* in_sizes, int n_in,
                              void* d_out, int out_size)
{
    const float* f0    = (const float*)d_in[0];
    const float* f1    = (const float*)d_in[1];
    const float* f2    = (const float*)d_in[2];
    const float* f3    = (const float*)d_in[3];
    const float* boxes = (const float*)d_in[4];
    const int*   imgs  = (const int*)d_in[5];
    float* out = (float*)d_out;

    const int N = in_sizes[4] / 4;   // 1000 boxes
    pooler_kernel<<<N * 4, BLOCK>>>(f0, f1, f2, f3, boxes, imgs, out);
}

// round 4
// speedup vs baseline: 2.1021x; 2.1021x over previous
#include <cuda_runtime.h>

// FPN Pooler: multi-level ROIAlign with warp-autonomous smem staging.
// feats NCHW f32: f0 [2,256,200,200], f1 [2,256,100,100], f2 [2,256,50,50], f3 [2,256,25,25]
// boxes [1000,4], img_ids [1000] -> out [1000,256,7,7] f32

#define P 14            // OUT*SR samples per axis
#define TILE_F 1440     // floats per warp tile (max footprint ~1150)
#define NWARP 8
#define BLOCK 256
#define CPB 128         // channels per block -> 2 blocks per box
#define CH_PER_WARP 16  // CPB / NWARP

__device__ __forceinline__ void cp_async4(float* smem_dst, const float* gmem_src) {
    unsigned s = (unsigned)__cvta_generic_to_shared(smem_dst);
    asm volatile("cp.async.ca.shared.global [%0], [%1], 4;\n" :: "r"(s), "l"(gmem_src));
}

__global__ __launch_bounds__(BLOCK) void pooler_kernel(
    const float* __restrict__ f0, const float* __restrict__ f1,
    const float* __restrict__ f2, const float* __restrict__ f3,
    const float* __restrict__ boxes, const int* __restrict__ img_ids,
    float* __restrict__ out)
{
    const int bx   = blockIdx.x;
    const int n    = bx >> 1;
    const int cq   = (bx & 1) * CPB;
    const int tid  = threadIdx.x;
    const int warp = tid >> 5, lane = tid & 31;

    __shared__ float s_tile[NWARP][TILE_F];
    __shared__ int   s_rx0[P], s_rx1[P], s_ry0[P], s_ry1[P];  // raw feature coords
    __shared__ int   s_cx0[P], s_cx1[P], s_oy0[P], s_oy1[P];  // tile-relative
    __shared__ float s_ax0[P], s_ax1[P], s_ay0[P], s_ay1[P];  // folded weights (incl 0.5*valid)

    // ---- per-box scalars (redundant per thread) ----
    const float bx1 = boxes[4*n+0], by1 = boxes[4*n+1];
    const float bx2 = boxes[4*n+2], by2 = boxes[4*n+3];
    const float sq  = sqrtf((bx2 - bx1) * (by2 - by1));
    float lf = floorf(4.0f + log2f(sq / 224.0f + 1e-6f));
    lf = fminf(fmaxf(lf, 2.0f), 5.0f);
    const int lvl = (int)lf - 2;

    int H, W; float scale; const float* fp;
    switch (lvl) {
        case 0:  H = 200; W = 200; scale = 0.25f;    fp = f0; break;
        case 1:  H = 100; W = 100; scale = 0.125f;   fp = f1; break;
        case 2:  H = 50;  W = 50;  scale = 0.0625f;  fp = f2; break;
        default: H = 25;  W = 25;  scale = 0.03125f; fp = f3; break;
    }
    const int HW  = H * W;
    const int img = __ldg(img_ids + n);
    const float* gbase = fp + (size_t)img * 256 * HW;

    const float rx1 = bx1 * scale, ry1 = by1 * scale;
    const float roi_w = fmaxf(bx2 * scale - rx1, 1.0f);
    const float roi_h = fmaxf(by2 * scale - ry1, 1.0f);
    const float bw = roi_w * (1.0f / 7.0f);
    const float bh = roi_h * (1.0f / 7.0f);

    // ---- phase 1: raw axis tables ----
    if (tid < P) {
        const int i = tid, p = i >> 1, r = i & 1;
        const float xg = rx1 + (float)p * bw + ((float)r + 0.5f) * bw * 0.5f;
        const float vx = (xg >= -1.0f && xg <= (float)W) ? 0.5f : 0.0f;
        float x = fminf(fmaxf(xg, 0.0f), (float)(W - 1));
        const int x0 = (int)x;
        s_rx0[i] = x0;
        s_rx1[i] = min(x0 + 1, W - 1);
        const float lx = x - (float)x0;
        s_ax0[i] = vx * (1.0f - lx);
        s_ax1[i] = vx * lx;
    } else if (tid >= 16 && tid < 16 + P) {
        const int i = tid - 16, p = i >> 1, r = i & 1;
        const float yg = ry1 + (float)p * bh + ((float)r + 0.5f) * bh * 0.5f;
        const float vy = (yg >= -1.0f && yg <= (float)H) ? 0.5f : 0.0f;
        float y = fminf(fmaxf(yg, 0.0f), (float)(H - 1));
        const int y0 = (int)y;
        s_ry0[i] = y0;
        s_ry1[i] = min(y0 + 1, H - 1);
        const float ly = y - (float)y0;
        s_ay0[i] = vy * (1.0f - ly);
        s_ay1[i] = vy * ly;
    }
    __syncthreads();

    const int clo = s_rx0[0],  rlo = s_ry0[0];
    const int nc  = s_rx1[P-1] - clo + 1;
    const int nr  = s_ry1[P-1] - rlo + 1;
    const int stride = nc | 1;

    // ---- phase 2: tile-relative tables (distinct arrays: no race) ----
    if (tid < P) {
        s_cx0[tid] = s_rx0[tid] - clo;
        s_cx1[tid] = s_rx1[tid] - clo;
    } else if (tid >= 16 && tid < 16 + P) {
        const int i = tid - 16;
        s_oy0[i] = (s_ry0[i] - rlo) * stride;
        s_oy1[i] = (s_ry1[i] - rlo) * stride;
    }
    __syncthreads();

    // ---- hoist per-bin geometry into registers (2 bins per lane) ----
    // bin0 = lane (0..31), bin1 = 32+lane (lane<17)
    int   oA0[2], oA1[2], oB0[2], oB1[2], cA0[2], cA1[2], cB0[2], cB1[2];
    float ayA0[2], ayA1[2], ayB0[2], ayB1[2], axA0[2], axA1[2], axB0[2], axB1[2];

    #pragma unroll
    for (int s = 0; s < 2; ++s) {
        const int bin = min(lane + 32 * s, 48);
        const int ph = bin / 7, pw = bin - ph * 7;
        const int iyA = 2*ph, iyB = iyA + 1;
        const int ixA = 2*pw, ixB = ixA + 1;
        oA0[s] = s_oy0[iyA]; oA1[s] = s_oy1[iyA];
        oB0[s] = s_oy0[iyB]; oB1[s] = s_oy1[iyB];
        cA0[s] = s_cx0[ixA]; cA1[s] = s_cx1[ixA];
        cB0[s] = s_cx0[ixB]; cB1[s] = s_cx1[ixB];
        ayA0[s] = s_ay0[iyA]; ayA1[s] = s_ay1[iyA];
        ayB0[s] = s_ay0[iyB]; ayB1[s] = s_ay1[iyB];
        axA0[s] = s_ax0[ixA]; axA1[s] = s_ax1[ixA];
        axB0[s] = s_ax0[ixB]; axB1[s] = s_ax1[ixB];
    }

    // ---- main loop: each warp autonomously stages + computes its channels ----
    float* tile = s_tile[warp];
    const int gRow0 = rlo * W + clo;
    const float* gch0 = gbase + gRow0 + (size_t)(cq + warp * CH_PER_WARP) * HW;
    float* outp = out + (size_t)n * 12544 + (size_t)(cq + warp * CH_PER_WARP) * 49;

    for (int it = 0; it < CH_PER_WARP; ++it) {
        const float* gp = gch0 + (size_t)it * HW;

        // stage window via cp.async (fire-and-forget, full MLP)
        for (int r = 0; r < nr; ++r) {
            const float* grow = gp + r * W;
            float* trow = tile + r * stride;
            for (int c = lane; c < nc; c += 32)
                cp_async4(trow + c, grow + c);
        }
        asm volatile("cp.async.commit_group;\n" ::: "memory");
        asm volatile("cp.async.wait_group 0;\n" ::: "memory");
        __syncwarp();

        // compute 2 bins per lane (Horner by feature row)
        #pragma unroll
        for (int s = 0; s < 2; ++s) {
            float rA0 = axA0[s] * tile[oA0[s] + cA0[s]];
            rA0 += axA1[s] * tile[oA0[s] + cA1[s]];
            rA0 += axB0[s] * tile[oA0[s] + cB0[s]];
            rA0 += axB1[s] * tile[oA0[s] + cB1[s]];
            float rA1 = axA0[s] * tile[oA1[s] + cA0[s]];
            rA1 += axA1[s] * tile[oA1[s] + cA1[s]];
            rA1 += axB0[s] * tile[oA1[s] + cB0[s]];
            rA1 += axB1[s] * tile[oA1[s] + cB1[s]];
            float rB0 = axA0[s] * tile[oB0[s] + cA0[s]];
            rB0 += axA1[s] * tile[oB0[s] + cA1[s]];
            rB0 += axB0[s] * tile[oB0[s] + cB0[s]];
            rB0 += axB1[s] * tile[oB0[s] + cB1[s]];
            float rB1 = axA0[s] * tile[oB1[s] + cA0[s]];
            rB1 += axA1[s] * tile[oB1[s] + cA1[s]];
            rB1 += axB0[s] * tile[oB1[s] + cB0[s]];
            rB1 += axB1[s] * tile[oB1[s] + cB1[s]];

            const float acc = ayA0[s] * rA0 + ayA1[s] * rA1
                            + ayB0[s] * rB0 + ayB1[s] * rB1;

            const int bin = lane + 32 * s;
            if (bin < 49) outp[bin] = acc;
        }
        outp += 49;
        __syncwarp();   // all lanes done reading tile before next stage
    }
}

extern "C" void kernel_launch(void* const* d_in, const int* in_sizes, int n_in,
                              void* d_out, int out_size)
{
    const float* f0    = (const float*)d_in[0];
    const float* f1    = (const float*)d_in[1];
    const float* f2    = (const float*)d_in[2];
    const float* f3    = (const float*)d_in[3];
    const float* boxes = (const float*)d_in[4];
    const int*   imgs  = (const int*)d_in[5];
    float* out = (float*)d_out;

    const int N = in_sizes[4] / 4;   // 1000 boxes
    pooler_kernel<<<N * 2, BLOCK>>>(f0, f1, f2, f3, boxes, imgs, out);
}